// round 1
// baseline (speedup 1.0000x reference)
#include <cuda_runtime.h>
#include <math.h>
#include <stdint.h>

// Problem dims (fixed by the dataset)
#define Bb 32
#define Ll 2048
#define Ee 1024
#define Uu 1024

// GEMM tiling
#define BM 128
#define BN 128
#define BK 16
#define LDA (BM + 8)   // 136 floats: k-stride*136 %32 = 8k -> conflict-free frag loads
#define LDB (BN + 8)

// Scratch (no cudaMalloc allowed)
__device__ float g_score[Bb * Ll];
__device__ float g_hW[Bb * Uu];

__device__ __forceinline__ float f2tf(float x) {
    unsigned r;
    asm("cvt.rna.tf32.f32 %0, %1;" : "=r"(r) : "f"(x));
    return __uint_as_float(r);
}

__device__ __forceinline__ void mma8(float d[4], const unsigned a[4], const unsigned b[2]) {
    asm volatile(
        "mma.sync.aligned.m16n8k8.row.col.f32.tf32.tf32.f32 "
        "{%0,%1,%2,%3},{%4,%5,%6,%7},{%8,%9},{%0,%1,%2,%3};"
        : "+f"(d[0]), "+f"(d[1]), "+f"(d[2]), "+f"(d[3])
        : "r"(a[0]), "r"(a[1]), "r"(a[2]), "r"(a[3]), "r"(b[0]), "r"(b[1]));
}

// ---------------------------------------------------------------------------
// Kernel 1: g_hW[b,u] = dec_hidden[b,:] @ Wh_k[:,u] + Ws_b[u] + Wh_b[u]
//                       + (use_cov ? Wc_b[u] : 0);   also zeroes g_score.
// grid (4, 32), 256 threads
// ---------------------------------------------------------------------------
__global__ void hw_kernel(const float* __restrict__ dec,
                          const float* __restrict__ Wh,
                          const float* __restrict__ Wsb,
                          const float* __restrict__ Whb,
                          const float* __restrict__ Wcb,
                          const int* __restrict__ ucp) {
    __shared__ float sdec[Ee];
    const int b = blockIdx.y;
    const int u = blockIdx.x * 256 + threadIdx.x;

    for (int e = threadIdx.x; e < Ee; e += 256) sdec[e] = dec[b * Ee + e];
    __syncthreads();

    float acc = 0.f;
#pragma unroll 8
    for (int e = 0; e < Ee; e++) acc += sdec[e] * Wh[e * Uu + u];

    const int uc = *ucp;
    g_hW[b * Uu + u] = acc + Wsb[u] + Whb[u] + (uc ? Wcb[u] : 0.f);

    // zero the score buffer: 4*32*256 = 32768 threads, 2 elems each = 65536
    const int idx = (blockIdx.y * gridDim.x + blockIdx.x) * 256 + threadIdx.x;
    g_score[idx * 2 + 0] = 0.f;
    g_score[idx * 2 + 1] = 0.f;
}

// ---------------------------------------------------------------------------
// Kernel 2: pre = enc[65536,1024] @ Ws[1024,1024] (+row/col terms),
//           fused epilogue: score[r] += sum_u tanh(pre[r,u]) * V[u]
// 256 threads = 8 warps (2M x 4N), warp tile 64x32, block tile 128x128
// ---------------------------------------------------------------------------
__global__ void __launch_bounds__(256, 1)
gemm_score(const float* __restrict__ enc,
           const float* __restrict__ Ws,
           const float* __restrict__ Wc,
           const float* __restrict__ Vk,
           const float* __restrict__ cov,
           const int* __restrict__ ucp) {
    __shared__ __align__(16) float As[2][BK][LDA];
    __shared__ __align__(16) float Bs[2][BK][LDB];

    const int tid  = threadIdx.x;
    const int warp = tid >> 5;
    const int lane = tid & 31;
    const int g    = lane >> 2;   // group id 0..7
    const int tig  = lane & 3;    // thread-in-group 0..3
    const int wm   = warp & 1;    // 0..1  (M)
    const int wn   = warp >> 1;   // 0..3  (N)

    const int rowBlock = blockIdx.y * BM;
    const int colBlock = blockIdx.x * BN;

    // staging assignments
    const int arow  = tid >> 1;          // 0..127
    const int akoff = (tid & 1) * 8;     // 0 or 8 (k offset)
    const int brow  = tid >> 4;          // 0..15  (k row)
    const int bc4   = tid & 15;          // float4 col slot

    const float* Ag = enc + (size_t)(rowBlock + arow) * Ee + akoff;
    const float* Bg = Ws + (size_t)brow * Uu + colBlock + bc4 * 4;

    float acc[4][4][4];
#pragma unroll
    for (int i = 0; i < 4; i++)
#pragma unroll
        for (int j = 0; j < 4; j++)
#pragma unroll
            for (int k = 0; k < 4; k++) acc[i][j][k] = 0.f;

    float4 ra0, ra1, rb0, rb1;

    // prologue: tile 0
    ra0 = *(const float4*)(Ag + 0);
    ra1 = *(const float4*)(Ag + 4);
    rb0 = *(const float4*)(Bg + 0);
    rb1 = *(const float4*)(Bg + 64);
    {
        float* as = &As[0][akoff][arow];
        as[0 * LDA] = f2tf(ra0.x); as[1 * LDA] = f2tf(ra0.y);
        as[2 * LDA] = f2tf(ra0.z); as[3 * LDA] = f2tf(ra0.w);
        as[4 * LDA] = f2tf(ra1.x); as[5 * LDA] = f2tf(ra1.y);
        as[6 * LDA] = f2tf(ra1.z); as[7 * LDA] = f2tf(ra1.w);
        float4 c0 = make_float4(f2tf(rb0.x), f2tf(rb0.y), f2tf(rb0.z), f2tf(rb0.w));
        float4 c1 = make_float4(f2tf(rb1.x), f2tf(rb1.y), f2tf(rb1.z), f2tf(rb1.w));
        *(float4*)&Bs[0][brow][bc4 * 4]      = c0;
        *(float4*)&Bs[0][brow][bc4 * 4 + 64] = c1;
    }
    __syncthreads();

    const int NK = Ee / BK;  // 64
    int buf = 0;

    for (int kt = 0; kt < NK; kt++) {
        if (kt + 1 < NK) {
            const float* An = Ag + (kt + 1) * BK;
            ra0 = *(const float4*)(An + 0);
            ra1 = *(const float4*)(An + 4);
            const float* Bn = Bg + (size_t)(kt + 1) * BK * Uu;
            rb0 = *(const float4*)(Bn + 0);
            rb1 = *(const float4*)(Bn + 64);
        }

        // compute on As[buf]/Bs[buf]
#pragma unroll
        for (int ks = 0; ks < 2; ks++) {
            const int k = ks * 8;
            unsigned af[4][4], bf[4][2];
#pragma unroll
            for (int mi = 0; mi < 4; mi++) {
                const int m = wm * 64 + mi * 16 + g;
                af[mi][0] = __float_as_uint(As[buf][k + tig][m]);
                af[mi][1] = __float_as_uint(As[buf][k + tig][m + 8]);
                af[mi][2] = __float_as_uint(As[buf][k + tig + 4][m]);
                af[mi][3] = __float_as_uint(As[buf][k + tig + 4][m + 8]);
            }
#pragma unroll
            for (int ni = 0; ni < 4; ni++) {
                const int n = wn * 32 + ni * 8 + g;
                bf[ni][0] = __float_as_uint(Bs[buf][k + tig][n]);
                bf[ni][1] = __float_as_uint(Bs[buf][k + tig + 4][n]);
            }
#pragma unroll
            for (int mi = 0; mi < 4; mi++)
#pragma unroll
                for (int ni = 0; ni < 4; ni++) mma8(acc[mi][ni], af[mi], bf[ni]);
        }

        if (kt + 1 < NK) {
            const int nb = buf ^ 1;
            float* as = &As[nb][akoff][arow];
            as[0 * LDA] = f2tf(ra0.x); as[1 * LDA] = f2tf(ra0.y);
            as[2 * LDA] = f2tf(ra0.z); as[3 * LDA] = f2tf(ra0.w);
            as[4 * LDA] = f2tf(ra1.x); as[5 * LDA] = f2tf(ra1.y);
            as[6 * LDA] = f2tf(ra1.z); as[7 * LDA] = f2tf(ra1.w);
            float4 c0 = make_float4(f2tf(rb0.x), f2tf(rb0.y), f2tf(rb0.z), f2tf(rb0.w));
            float4 c1 = make_float4(f2tf(rb1.x), f2tf(rb1.y), f2tf(rb1.z), f2tf(rb1.w));
            *(float4*)&Bs[nb][brow][bc4 * 4]      = c0;
            *(float4*)&Bs[nb][brow][bc4 * 4 + 64] = c1;
            __syncthreads();
            buf ^= 1;
        }
    }

    // ---------- fused epilogue: tanh(pre) @ V, row-sum, atomic into score ----
    const int uc = *ucp;
    const int bIdx = rowBlock >> 11;  // rowBlock / L (L=2048)

    // per-thread row coverage values
    float cv[4][2];
#pragma unroll
    for (int mi = 0; mi < 4; mi++) {
        const int r0 = rowBlock + wm * 64 + mi * 16 + g;
        cv[mi][0] = uc ? cov[r0] : 0.f;
        cv[mi][1] = uc ? cov[r0 + 8] : 0.f;
    }

    float rs[4][2];
#pragma unroll
    for (int mi = 0; mi < 4; mi++) { rs[mi][0] = 0.f; rs[mi][1] = 0.f; }

#pragma unroll
    for (int ni = 0; ni < 4; ni++) {
        const int u0 = colBlock + wn * 32 + ni * 8 + 2 * tig;
        const float bias0 = g_hW[bIdx * Uu + u0];
        const float bias1 = g_hW[bIdx * Uu + u0 + 1];
        const float wc0 = uc ? Wc[u0] : 0.f;
        const float wc1 = uc ? Wc[u0 + 1] : 0.f;
        const float v0 = Vk[u0];
        const float v1 = Vk[u0 + 1];
#pragma unroll
        for (int mi = 0; mi < 4; mi++) {
            float p00 = acc[mi][ni][0] + bias0 + cv[mi][0] * wc0;
            float p01 = acc[mi][ni][1] + bias1 + cv[mi][0] * wc1;
            float p10 = acc[mi][ni][2] + bias0 + cv[mi][1] * wc0;
            float p11 = acc[mi][ni][3] + bias1 + cv[mi][1] * wc1;
            rs[mi][0] += tanhf(p00) * v0 + tanhf(p01) * v1;
            rs[mi][1] += tanhf(p10) * v0 + tanhf(p11) * v1;
        }
    }

#pragma unroll
    for (int mi = 0; mi < 4; mi++) {
#pragma unroll
        for (int h = 0; h < 2; h++) {
            float s = rs[mi][h];
            s += __shfl_xor_sync(0xFFFFFFFFu, s, 1);
            s += __shfl_xor_sync(0xFFFFFFFFu, s, 2);
            if (tig == 0) {
                const int r = rowBlock + wm * 64 + mi * 16 + g + h * 8;
                atomicAdd(&g_score[r], s);
            }
        }
    }
}

// ---------------------------------------------------------------------------
// Kernel 3: masked softmax over L per batch; writes attn and coverage outputs
// grid 32, 256 threads (8 elems/thread)
// ---------------------------------------------------------------------------
__global__ void softmax_kernel(const float* __restrict__ cov,
                               const float* __restrict__ Vb,
                               const int* __restrict__ mask,
                               const int* __restrict__ ucp,
                               float* __restrict__ attn,
                               float* __restrict__ covOut) {
    __shared__ float red[256];
    const int b = blockIdx.x;
    const int tid = threadIdx.x;
    const float vb = Vb[0];
    const int uc = *ucp;

    float vals[8];
    float mx = -INFINITY;
#pragma unroll
    for (int i = 0; i < 8; i++) {
        const int l = tid + i * 256;
        const float s = (g_score[b * Ll + l] + vb) * (float)mask[b * Ll + l];
        vals[i] = s;
        mx = fmaxf(mx, s);
    }
    red[tid] = mx;
    __syncthreads();
    for (int s = 128; s > 0; s >>= 1) {
        if (tid < s) red[tid] = fmaxf(red[tid], red[tid + s]);
        __syncthreads();
    }
    mx = red[0];
    __syncthreads();

    float sum = 0.f;
#pragma unroll
    for (int i = 0; i < 8; i++) {
        vals[i] = expf(vals[i] - mx);
        sum += vals[i];
    }
    red[tid] = sum;
    __syncthreads();
    for (int s = 128; s > 0; s >>= 1) {
        if (tid < s) red[tid] += red[tid + s];
        __syncthreads();
    }
    const float inv = 1.f / red[0];

#pragma unroll
    for (int i = 0; i < 8; i++) {
        const int l = tid + i * 256;
        const float w = vals[i] * inv;
        attn[b * Ll + l] = w;
        covOut[b * Ll + l] = w + (uc ? cov[b * Ll + l] : 0.f);
    }
}

// ---------------------------------------------------------------------------
// Kernel 4: context[b,e] = sum_l attn[b,l] * enc[b,l,e]
// grid (4, 32), 256 threads
// ---------------------------------------------------------------------------
__global__ void context_kernel(const float* __restrict__ enc,
                               const float* __restrict__ attn,
                               float* __restrict__ ctx) {
    __shared__ float w[Ll];
    const int b = blockIdx.y;
    const int e = blockIdx.x * 256 + threadIdx.x;

    for (int l = threadIdx.x; l < Ll; l += 256) w[l] = attn[b * Ll + l];
    __syncthreads();

    float acc = 0.f;
    const float* ep = enc + (size_t)b * Ll * Ee + e;
#pragma unroll 8
    for (int l = 0; l < Ll; l++) acc += w[l] * ep[(size_t)l * Ee];

    ctx[b * Ee + e] = acc;
}

// ---------------------------------------------------------------------------
extern "C" void kernel_launch(void* const* d_in, const int* in_sizes, int n_in,
                              void* d_out, int out_size) {
    const float* dec  = (const float*)d_in[0];
    const float* enc  = (const float*)d_in[1];
    const float* cov  = (const float*)d_in[2];
    const float* Wsk  = (const float*)d_in[3];
    const float* Wsb  = (const float*)d_in[4];
    const float* Whk  = (const float*)d_in[5];
    const float* Whb  = (const float*)d_in[6];
    const float* Wck  = (const float*)d_in[7];
    const float* Wcb  = (const float*)d_in[8];
    const float* Vk   = (const float*)d_in[9];
    const float* Vb   = (const float*)d_in[10];
    const int*   mask = (const int*)d_in[11];
    const int*   ucp  = (const int*)d_in[12];

    float* out    = (float*)d_out;
    float* ctx    = out;                       // [32, 1024]
    float* attn   = out + Bb * Ee;             // [32, 2048]
    float* covOut = attn + Bb * Ll;            // [32, 2048]

    hw_kernel<<<dim3(4, 32), 256>>>(dec, Whk, Wsb, Whb, Wcb, ucp);
    gemm_score<<<dim3(Uu / BN, (Bb * Ll) / BM), 256>>>(enc, Wsk, Wck, Vk, cov, ucp);
    softmax_kernel<<<Bb, 256>>>(cov, Vb, mask, ucp, attn, covOut);
    context_kernel<<<dim3(Ee / 256, Bb), 256>>>(enc, attn, ctx);
}

// round 3
// speedup vs baseline: 1.0485x; 1.0485x over previous
#include <cuda_runtime.h>
#include <math.h>
#include <stdint.h>

// Problem dims (fixed by the dataset)
#define Bb 32
#define Ll 2048
#define Ee 1024
#define Uu 1024

// GEMM tiling
#define BM 128
#define BN 256
#define BK 16
#define NKT (Ee / BK)            // 64 k-tiles
#define STRIDE 20                // floats per smem row (16 + 4 pad) -> conflict-free frags
#define A_STAGE_FLOATS (BM * STRIDE)          // 2560
#define B_STAGE_FLOATS (BN * STRIDE)          // 5120
#define STAGE_BYTES ((A_STAGE_FLOATS + B_STAGE_FLOATS) * 4)   // 30720
#define NSTAGE 4
#define SM_TILES_BYTES (NSTAGE * STAGE_BYTES)                  // 122880
#define SM_BIAS_OFF (SM_TILES_BYTES)                           // 256 floats
#define SM_WC_OFF   (SM_BIAS_OFF + 1024)
#define SM_V_OFF    (SM_WC_OFF + 1024)
#define SM_ROW_OFF  (SM_V_OFF + 1024)                          // 128 floats
#define SMEM_TOTAL  (SM_ROW_OFF + 512)                         // 126464 bytes

// Scratch (no cudaMalloc allowed)
__device__ float g_score[Bb * Ll];
__device__ float g_hW[Bb * Uu];
__device__ float g_WsT[Uu * Ee];   // transposed Ws (rna-rounded to tf32)

// ---------------------------------------------------------------------------
__device__ __forceinline__ uint32_t smem_to_u32(const void* p) {
    uint32_t a;
    asm("{ .reg .u64 t; cvta.to.shared.u64 t, %1; cvt.u32.u64 %0, t; }" : "=r"(a) : "l"(p));
    return a;
}
__device__ __forceinline__ void cp16(uint32_t dst, const float* src) {
    asm volatile("cp.async.cg.shared.global [%0], [%1], 16;" :: "r"(dst), "l"(src) : "memory");
}
#define CP_COMMIT() asm volatile("cp.async.commit_group;" ::: "memory")
#define CP_WAIT2()  asm volatile("cp.async.wait_group 2;" ::: "memory")
#define CP_WAIT0()  asm volatile("cp.async.wait_group 0;" ::: "memory")

__device__ __forceinline__ void mma8(float d[4], const unsigned a[4], const unsigned b[2]) {
    asm volatile(
        "mma.sync.aligned.m16n8k8.row.col.f32.tf32.tf32.f32 "
        "{%0,%1,%2,%3},{%4,%5,%6,%7},{%8,%9},{%0,%1,%2,%3};"
        : "+f"(d[0]), "+f"(d[1]), "+f"(d[2]), "+f"(d[3])
        : "r"(a[0]), "r"(a[1]), "r"(a[2]), "r"(a[3]), "r"(b[0]), "r"(b[1]));
}

__device__ __forceinline__ float f2tf(float x) {
    unsigned r;
    asm("cvt.rna.tf32.f32 %0, %1;" : "=r"(r) : "f"(x));
    return __uint_as_float(r);
}

__device__ __forceinline__ float fast_tanh(float x) {
    const float t = __expf(2.f * x);              // inf for large x -> returns 1
    return 1.f - __fdividef(2.f, t + 1.f);        // t->0 for very neg x -> returns -1
}

// ---------------------------------------------------------------------------
// Kernel 0: WsT[u][e] = rna_tf32(Ws[e][u]).  grid (32,32), block (32,8)
// ---------------------------------------------------------------------------
__global__ void transpose_ws(const float* __restrict__ Ws) {
    __shared__ float t[32][33];
    const int bx = blockIdx.x, by = blockIdx.y;
    const int tx = threadIdx.x, ty = threadIdx.y;
#pragma unroll
    for (int j = 0; j < 4; j++)
        t[ty + j * 8][tx] = Ws[(size_t)(by * 32 + ty + j * 8) * Uu + bx * 32 + tx];
    __syncthreads();
#pragma unroll
    for (int j = 0; j < 4; j++)
        g_WsT[(size_t)(bx * 32 + ty + j * 8) * Ee + by * 32 + tx] = f2tf(t[tx][ty + j * 8]);
}

// ---------------------------------------------------------------------------
// Kernel 1: g_hW[b,u] = dec[b,:]@Wh[:,u] + Ws_b + Wh_b (+Wc_b); zero score & ctx
// grid (4, 32), 256 threads
// ---------------------------------------------------------------------------
__global__ void hw_kernel(const float* __restrict__ dec,
                          const float* __restrict__ Wh,
                          const float* __restrict__ Wsb,
                          const float* __restrict__ Whb,
                          const float* __restrict__ Wcb,
                          const int* __restrict__ ucp,
                          float* __restrict__ ctx) {
    __shared__ float sdec[Ee];
    const int b = blockIdx.y;
    const int u = blockIdx.x * 256 + threadIdx.x;

    for (int e = threadIdx.x; e < Ee; e += 256) sdec[e] = dec[b * Ee + e];
    __syncthreads();

    float acc = 0.f;
#pragma unroll 8
    for (int e = 0; e < Ee; e++) acc += sdec[e] * Wh[(size_t)e * Uu + u];

    const int uc = *ucp;
    g_hW[b * Uu + u] = acc + Wsb[u] + Whb[u] + (uc ? Wcb[u] : 0.f);

    const int idx = (blockIdx.y * gridDim.x + blockIdx.x) * 256 + threadIdx.x; // 0..32767
    g_score[idx * 2 + 0] = 0.f;
    g_score[idx * 2 + 1] = 0.f;
    ctx[idx] = 0.f;
}

// ---------------------------------------------------------------------------
// Kernel 2: tf32 mma.sync GEMM (128x256 block, 16 warps of 64x32) + fused
// tanh/V epilogue -> score.  grid (4, 512), 512 threads, 4-stage cp.async.
// ---------------------------------------------------------------------------
__device__ __forceinline__ void stage_tile(uint32_t smBase, int buf,
                                           const float* __restrict__ aG,
                                           const float* __restrict__ bG,
                                           int kt, int tid) {
    const uint32_t st = smBase + buf * STAGE_BYTES;
    // A: 128 rows x 4 chunks = 512 chunks, 1 per thread
    {
        const int m = tid >> 2, ch = tid & 3;
        cp16(st + m * (STRIDE * 4) + ch * 16,
             aG + (size_t)m * Ee + kt * BK + ch * 4);
    }
    // B: 256 rows x 4 chunks = 1024 chunks, 2 per thread
    const uint32_t bOff = st + A_STAGE_FLOATS * 4;
#pragma unroll
    for (int i = 0; i < 2; i++) {
        const int c = tid + i * 512;
        const int n = c >> 2, ch = c & 3;
        cp16(bOff + n * (STRIDE * 4) + ch * 16,
             bG + (size_t)n * Ee + kt * BK + ch * 4);
    }
}

__global__ void __launch_bounds__(512, 1)
gemm_score_mma(const float* __restrict__ enc,
               const float* __restrict__ Wc,
               const float* __restrict__ Vk,
               const float* __restrict__ cov,
               const int* __restrict__ ucp) {
    extern __shared__ char smem[];
    const uint32_t smBase = smem_to_u32(smem);
    const int tid  = threadIdx.x;
    const int wid  = tid >> 5;
    const int lane = tid & 31;
    const int g    = lane >> 2;
    const int tig  = lane & 3;
    const int wm   = wid >> 3;     // 0..1 (M)
    const int wn   = wid & 7;      // 0..7 (N)

    const int rowBase = blockIdx.y * BM;
    const int colBase = blockIdx.x * BN;
    const int b = rowBase >> 11;
    const int uc = *ucp;

    float* sBias = (float*)(smem + SM_BIAS_OFF);
    float* sWc   = (float*)(smem + SM_WC_OFF);
    float* sV    = (float*)(smem + SM_V_OFF);
    float* sRow  = (float*)(smem + SM_ROW_OFF);

    if (tid < 256) {
        const int u = colBase + tid;
        sBias[tid] = g_hW[b * Uu + u];
        sWc[tid]   = uc ? Wc[u] : 0.f;
        sV[tid]    = Vk[u];
    }
    if (tid < 128) sRow[tid] = 0.f;

    const float* aG = enc + (size_t)rowBase * Ee;
    const float* bG = g_WsT + (size_t)colBase * Ee;

    // prologue: stage 0..2
    stage_tile(smBase, 0, aG, bG, 0, tid); CP_COMMIT();
    stage_tile(smBase, 1, aG, bG, 1, tid); CP_COMMIT();
    stage_tile(smBase, 2, aG, bG, 2, tid); CP_COMMIT();

    float acc[4][4][4];
#pragma unroll
    for (int i = 0; i < 4; i++)
#pragma unroll
        for (int j = 0; j < 4; j++)
#pragma unroll
            for (int k = 0; k < 4; k++) acc[i][j][k] = 0.f;

    for (int kt = 0; kt < NKT; kt++) {
        const int buf = kt & 3;
        CP_WAIT2();
        __syncthreads();

        if (kt + 3 < NKT) stage_tile(smBase, (kt + 3) & 3, aG, bG, kt + 3, tid);
        CP_COMMIT();   // always commit (possibly empty) to keep wait_group math

        const float* sA = (const float*)(smem + buf * STAGE_BYTES);
        const float* sB = sA + A_STAGE_FLOATS;

#pragma unroll
        for (int slice = 0; slice < 2; slice++) {
            const int kk = slice * 8;
            unsigned af[4][4], bf[4][2];
#pragma unroll
            for (int mi = 0; mi < 4; mi++) {
                const float* p = sA + (wm * 64 + mi * 16 + g) * STRIDE + kk + tig;
                af[mi][0] = __float_as_uint(p[0]);
                af[mi][1] = __float_as_uint(p[8 * STRIDE]);
                af[mi][2] = __float_as_uint(p[4]);
                af[mi][3] = __float_as_uint(p[8 * STRIDE + 4]);
            }
#pragma unroll
            for (int ni = 0; ni < 4; ni++) {
                const float* q = sB + (wn * 32 + ni * 8 + g) * STRIDE + kk + tig;
                bf[ni][0] = __float_as_uint(q[0]);
                bf[ni][1] = __float_as_uint(q[4]);
            }
#pragma unroll
            for (int mi = 0; mi < 4; mi++)
#pragma unroll
                for (int ni = 0; ni < 4; ni++) mma8(acc[mi][ni], af[mi], bf[ni]);
        }
    }
    CP_WAIT0();

    // ---------------- fused epilogue ----------------
#pragma unroll
    for (int mi = 0; mi < 4; mi++) {
        const int r0 = wm * 64 + mi * 16 + g;
        const int r1 = r0 + 8;
        const float cv0 = uc ? cov[rowBase + r0] : 0.f;
        const float cv1 = uc ? cov[rowBase + r1] : 0.f;
        float s0 = 0.f, s1 = 0.f;
#pragma unroll
        for (int ni = 0; ni < 4; ni++) {
            const int c0 = wn * 32 + ni * 8 + 2 * tig;
            const int c1 = c0 + 1;
            const float b0 = sBias[c0], b1 = sBias[c1];
            const float w0 = sWc[c0],  w1 = sWc[c1];
            const float v0 = sV[c0],   v1 = sV[c1];
            s0 += fast_tanh(acc[mi][ni][0] + b0 + cv0 * w0) * v0
                + fast_tanh(acc[mi][ni][1] + b1 + cv0 * w1) * v1;
            s1 += fast_tanh(acc[mi][ni][2] + b0 + cv1 * w0) * v0
                + fast_tanh(acc[mi][ni][3] + b1 + cv1 * w1) * v1;
        }
        s0 += __shfl_xor_sync(0xFFFFFFFFu, s0, 1);
        s0 += __shfl_xor_sync(0xFFFFFFFFu, s0, 2);
        s1 += __shfl_xor_sync(0xFFFFFFFFu, s1, 1);
        s1 += __shfl_xor_sync(0xFFFFFFFFu, s1, 2);
        if (tig == 0) {
            atomicAdd(&sRow[r0], s0);
            atomicAdd(&sRow[r1], s1);
        }
    }
    __syncthreads();
    if (tid < 128) atomicAdd(&g_score[rowBase + tid], sRow[tid]);
}

// ---------------------------------------------------------------------------
// Kernel 3: masked softmax over L per batch; writes attn and coverage outputs
// ---------------------------------------------------------------------------
__global__ void softmax_kernel(const float* __restrict__ cov,
                               const float* __restrict__ Vb,
                               const int* __restrict__ mask,
                               const int* __restrict__ ucp,
                               float* __restrict__ attn,
                               float* __restrict__ covOut) {
    __shared__ float red[256];
    const int b = blockIdx.x;
    const int tid = threadIdx.x;
    const float vb = Vb[0];
    const int uc = *ucp;

    float vals[8];
    float mx = -INFINITY;
#pragma unroll
    for (int i = 0; i < 8; i++) {
        const int l = tid + i * 256;
        const float s = (g_score[b * Ll + l] + vb) * (float)mask[b * Ll + l];
        vals[i] = s;
        mx = fmaxf(mx, s);
    }
    red[tid] = mx;
    __syncthreads();
    for (int s = 128; s > 0; s >>= 1) {
        if (tid < s) red[tid] = fmaxf(red[tid], red[tid + s]);
        __syncthreads();
    }
    mx = red[0];
    __syncthreads();

    float sum = 0.f;
#pragma unroll
    for (int i = 0; i < 8; i++) {
        vals[i] = expf(vals[i] - mx);
        sum += vals[i];
    }
    red[tid] = sum;
    __syncthreads();
    for (int s = 128; s > 0; s >>= 1) {
        if (tid < s) red[tid] += red[tid + s];
        __syncthreads();
    }
    const float inv = 1.f / red[0];

#pragma unroll
    for (int i = 0; i < 8; i++) {
        const int l = tid + i * 256;
        const float w = vals[i] * inv;
        attn[b * Ll + l] = w;
        covOut[b * Ll + l] = w + (uc ? cov[b * Ll + l] : 0.f);
    }
}

// ---------------------------------------------------------------------------
// Kernel 4: context[b,e] += sum_{l in chunk} attn[b,l] * enc[b,l,e]
// grid (32, 32), 256 threads, float4, atomics into pre-zeroed ctx
// ---------------------------------------------------------------------------
__global__ void __launch_bounds__(256)
context_kernel(const float* __restrict__ enc,
               const float* __restrict__ attn,
               float* __restrict__ ctx) {
    __shared__ float w[64];
    const int b = blockIdx.y;
    const int l0 = blockIdx.x * 64;
    if (threadIdx.x < 64) w[threadIdx.x] = attn[b * Ll + l0 + threadIdx.x];
    __syncthreads();

    const float4* ep = (const float4*)(enc + ((size_t)b * Ll + l0) * Ee) + threadIdx.x;
    float4 acc = make_float4(0.f, 0.f, 0.f, 0.f);
#pragma unroll 4
    for (int l = 0; l < 64; l++) {
        const float wv = w[l];
        const float4 v = ep[(size_t)l * 256];
        acc.x += wv * v.x; acc.y += wv * v.y; acc.z += wv * v.z; acc.w += wv * v.w;
    }
    float* c = ctx + b * Ee + threadIdx.x * 4;
    atomicAdd(c + 0, acc.x);
    atomicAdd(c + 1, acc.y);
    atomicAdd(c + 2, acc.z);
    atomicAdd(c + 3, acc.w);
}

// ---------------------------------------------------------------------------
extern "C" void kernel_launch(void* const* d_in, const int* in_sizes, int n_in,
                              void* d_out, int out_size) {
    const float* dec  = (const float*)d_in[0];
    const float* enc  = (const float*)d_in[1];
    const float* cov  = (const float*)d_in[2];
    const float* Wsk  = (const float*)d_in[3];
    const float* Wsb  = (const float*)d_in[4];
    const float* Whk  = (const float*)d_in[5];
    const float* Whb  = (const float*)d_in[6];
    const float* Wck  = (const float*)d_in[7];
    const float* Wcb  = (const float*)d_in[8];
    const float* Vk   = (const float*)d_in[9];
    const float* Vb   = (const float*)d_in[10];
    const int*   mask = (const int*)d_in[11];
    const int*   ucp  = (const int*)d_in[12];

    float* out    = (float*)d_out;
    float* ctx    = out;                       // [32, 1024]
    float* attn   = out + Bb * Ee;             // [32, 2048]
    float* covOut = attn + Bb * Ll;            // [32, 2048]

    cudaFuncSetAttribute(gemm_score_mma, cudaFuncAttributeMaxDynamicSharedMemorySize,
                         SMEM_TOTAL);

    transpose_ws<<<dim3(32, 32), dim3(32, 8)>>>(Wsk);
    hw_kernel<<<dim3(4, 32), 256>>>(dec, Whk, Wsb, Whb, Wcb, ucp, ctx);
    gemm_score_mma<<<dim3(Uu / BN, (Bb * Ll) / BM), 512, SMEM_TOTAL>>>(
        enc, Wck, Vk, cov, ucp);
    softmax_kernel<<<Bb, 256>>>(cov, Vb, mask, ucp, attn, covOut);
    context_kernel<<<dim3(32, Bb), 256>>>(enc, attn, ctx);
}

// round 4
// speedup vs baseline: 2.9362x; 2.8003x over previous
#include <cuda_runtime.h>
#include <cuda_fp16.h>
#include <math.h>
#include <stdint.h>

// Problem dims (fixed by the dataset)
#define Bb 32
#define Ll 2048
#define Ee 1024
#define Uu 1024

// GEMM tiling (fp16 mma.sync m16n8k16)
#define BM 128
#define BN 256
#define BKH 32                       // 32 halves per k-tile (64B data per row)
#define NKT (Ee / BKH)               // 32 k-tiles
#define ROWB 80                      // 64B data + 16B pad -> conflict-free ldmatrix
#define A_STAGE_BYTES (BM * ROWB)    // 10240
#define B_STAGE_BYTES (BN * ROWB)    // 20480
#define STAGE_BYTES (A_STAGE_BYTES + B_STAGE_BYTES)   // 30720
#define NSTAGE 4
#define SM_TILES_BYTES (NSTAGE * STAGE_BYTES)          // 122880
#define SM_BIAS_OFF (SM_TILES_BYTES)
#define SM_WC_OFF   (SM_BIAS_OFF + 1024)
#define SM_V_OFF    (SM_WC_OFF + 1024)
#define SM_ROW_OFF  (SM_V_OFF + 1024)
#define SMEM_TOTAL  (SM_ROW_OFF + 512)                 // 126464 bytes

// Scratch (no cudaMalloc allowed)
__device__ float  g_score[Bb * Ll];
__device__ float  g_hW[Bb * Uu];
__device__ __half g_encH[(size_t)Bb * Ll * Ee];   // fp16 copy of enc (128MB)
__device__ __half g_WsTH[Uu * Ee];                // transposed Ws in fp16

// ---------------------------------------------------------------------------
__device__ __forceinline__ uint32_t smem_to_u32(const void* p) {
    uint32_t a;
    asm("{ .reg .u64 t; cvta.to.shared.u64 t, %1; cvt.u32.u64 %0, t; }" : "=r"(a) : "l"(p));
    return a;
}
__device__ __forceinline__ void cp16(uint32_t dst, const void* src) {
    asm volatile("cp.async.cg.shared.global [%0], [%1], 16;" :: "r"(dst), "l"(src) : "memory");
}
#define CP_COMMIT() asm volatile("cp.async.commit_group;" ::: "memory")
#define CP_WAIT2()  asm volatile("cp.async.wait_group 2;" ::: "memory")
#define CP_WAIT0()  asm volatile("cp.async.wait_group 0;" ::: "memory")

__device__ __forceinline__ void ldsm4(unsigned& r0, unsigned& r1, unsigned& r2,
                                      unsigned& r3, uint32_t addr) {
    asm volatile("ldmatrix.sync.aligned.m8n8.x4.shared.b16 {%0,%1,%2,%3}, [%4];"
                 : "=r"(r0), "=r"(r1), "=r"(r2), "=r"(r3) : "r"(addr));
}

__device__ __forceinline__ void mma16(float d[4], const unsigned a[4], const unsigned b[2]) {
    asm volatile(
        "mma.sync.aligned.m16n8k16.row.col.f32.f16.f16.f32 "
        "{%0,%1,%2,%3},{%4,%5,%6,%7},{%8,%9},{%0,%1,%2,%3};"
        : "+f"(d[0]), "+f"(d[1]), "+f"(d[2]), "+f"(d[3])
        : "r"(a[0]), "r"(a[1]), "r"(a[2]), "r"(a[3]), "r"(b[0]), "r"(b[1]));
}

__device__ __forceinline__ float fast_tanh(float x) {
    const float t = __expf(2.f * x);
    return 1.f - __fdividef(2.f, t + 1.f);
}

// ---------------------------------------------------------------------------
// Kernel 0a: enc -> fp16 copy. 8 floats/thread, grid 32768 x 256
// ---------------------------------------------------------------------------
__global__ void __launch_bounds__(256)
conv_enc(const float* __restrict__ enc) {
    const size_t i = ((size_t)blockIdx.x * 256 + threadIdx.x) * 8;
    const float4 v0 = *(const float4*)(enc + i);
    const float4 v1 = *(const float4*)(enc + i + 4);
    __half2 h0 = __floats2half2_rn(v0.x, v0.y);
    __half2 h1 = __floats2half2_rn(v0.z, v0.w);
    __half2 h2 = __floats2half2_rn(v1.x, v1.y);
    __half2 h3 = __floats2half2_rn(v1.z, v1.w);
    uint4 o;
    o.x = *(uint32_t*)&h0; o.y = *(uint32_t*)&h1;
    o.z = *(uint32_t*)&h2; o.w = *(uint32_t*)&h3;
    *(uint4*)(g_encH + i) = o;
}

// ---------------------------------------------------------------------------
// Kernel 0b: WsTH[u][e] = half(Ws[e][u]).  grid (32,32), block (32,8)
// ---------------------------------------------------------------------------
__global__ void transpose_ws(const float* __restrict__ Ws) {
    __shared__ float t[32][33];
    const int bx = blockIdx.x, by = blockIdx.y;
    const int tx = threadIdx.x, ty = threadIdx.y;
#pragma unroll
    for (int j = 0; j < 4; j++)
        t[ty + j * 8][tx] = Ws[(size_t)(by * 32 + ty + j * 8) * Uu + bx * 32 + tx];
    __syncthreads();
#pragma unroll
    for (int j = 0; j < 4; j++)
        g_WsTH[(size_t)(bx * 32 + ty + j * 8) * Ee + by * 32 + tx] =
            __float2half_rn(t[tx][ty + j * 8]);
}

// ---------------------------------------------------------------------------
// Kernel 1: g_hW[b,u] = dec[b,:]@Wh[:,u] + Ws_b + Wh_b (+Wc_b); zero score & ctx
// ---------------------------------------------------------------------------
__global__ void hw_kernel(const float* __restrict__ dec,
                          const float* __restrict__ Wh,
                          const float* __restrict__ Wsb,
                          const float* __restrict__ Whb,
                          const float* __restrict__ Wcb,
                          const int* __restrict__ ucp,
                          float* __restrict__ ctx) {
    __shared__ float sdec[Ee];
    const int b = blockIdx.y;
    const int u = blockIdx.x * 256 + threadIdx.x;

    for (int e = threadIdx.x; e < Ee; e += 256) sdec[e] = dec[b * Ee + e];
    __syncthreads();

    float acc = 0.f;
#pragma unroll 8
    for (int e = 0; e < Ee; e++) acc += sdec[e] * Wh[(size_t)e * Uu + u];

    const int uc = *ucp;
    g_hW[b * Uu + u] = acc + Wsb[u] + Whb[u] + (uc ? Wcb[u] : 0.f);

    const int idx = (blockIdx.y * gridDim.x + blockIdx.x) * 256 + threadIdx.x;
    g_score[idx * 2 + 0] = 0.f;
    g_score[idx * 2 + 1] = 0.f;
    ctx[idx] = 0.f;
}

// ---------------------------------------------------------------------------
// Kernel 2: fp16 mma.sync GEMM (128x256 block, 16 warps of 64x32) + fused
// tanh/V epilogue -> score.  512 threads, 4-stage cp.async, ldmatrix frags.
// ---------------------------------------------------------------------------
__device__ __forceinline__ void stage_tile(uint32_t smBase, int buf,
                                           const __half* __restrict__ aG,
                                           const __half* __restrict__ bG,
                                           int kt, int tid) {
    const uint32_t st = smBase + buf * STAGE_BYTES;
    {
        const int r = tid >> 2, ch = tid & 3;
        cp16(st + r * ROWB + ch * 16, aG + (size_t)r * Ee + kt * BKH + ch * 8);
    }
    const uint32_t bO = st + A_STAGE_BYTES;
#pragma unroll
    for (int i = 0; i < 2; i++) {
        const int c = tid + i * 512;
        const int r = c >> 2, ch = c & 3;
        cp16(bO + r * ROWB + ch * 16, bG + (size_t)r * Ee + kt * BKH + ch * 8);
    }
}

__global__ void __launch_bounds__(512, 1)
gemm_score_h(const float* __restrict__ Wc,
             const float* __restrict__ Vk,
             const float* __restrict__ cov,
             const int* __restrict__ ucp) {
    extern __shared__ char smem[];
    const uint32_t smBase = smem_to_u32(smem);
    const int tid  = threadIdx.x;
    const int wid  = tid >> 5;
    const int lane = tid & 31;
    const int g    = lane >> 2;
    const int tig  = lane & 3;
    const int wm   = wid >> 3;     // 0..1 (M)
    const int wn   = wid & 7;      // 0..7 (N)

    const int rowBase = blockIdx.y * BM;
    const int colBase = blockIdx.x * BN;
    const int b = rowBase >> 11;
    const int uc = *ucp;

    float* sBias = (float*)(smem + SM_BIAS_OFF);
    float* sWc   = (float*)(smem + SM_WC_OFF);
    float* sV    = (float*)(smem + SM_V_OFF);
    float* sRow  = (float*)(smem + SM_ROW_OFF);

    if (tid < 256) {
        const int u = colBase + tid;
        sBias[tid] = g_hW[b * Uu + u];
        sWc[tid]   = uc ? Wc[u] : 0.f;
        sV[tid]    = Vk[u];
    }
    if (tid < 128) sRow[tid] = 0.f;

    const __half* aG = g_encH + (size_t)rowBase * Ee;
    const __half* bG = g_WsTH + (size_t)colBase * Ee;

    // ldmatrix lane-address components (relative to tile bases)
    const uint32_t aLane = (uint32_t)((lane & 15) * ROWB + (lane >> 4) * 16);
    const uint32_t bLane = (uint32_t)((((lane >> 4) << 3) + (lane & 7)) * ROWB
                                      + ((lane >> 3) & 1) * 16);

    stage_tile(smBase, 0, aG, bG, 0, tid); CP_COMMIT();
    stage_tile(smBase, 1, aG, bG, 1, tid); CP_COMMIT();
    stage_tile(smBase, 2, aG, bG, 2, tid); CP_COMMIT();

    float acc[4][4][4];
#pragma unroll
    for (int i = 0; i < 4; i++)
#pragma unroll
        for (int j = 0; j < 4; j++)
#pragma unroll
            for (int k = 0; k < 4; k++) acc[i][j][k] = 0.f;

    for (int kt = 0; kt < NKT; kt++) {
        const int buf = kt & 3;
        CP_WAIT2();
        __syncthreads();

        if (kt + 3 < NKT) stage_tile(smBase, (kt + 3) & 3, aG, bG, kt + 3, tid);
        CP_COMMIT();   // possibly-empty commit keeps wait_group arithmetic valid

        const uint32_t sA = smBase + buf * STAGE_BYTES;
        const uint32_t sB = sA + A_STAGE_BYTES;

#pragma unroll
        for (int s = 0; s < 2; s++) {
            unsigned af[4][4], bf[4][2];
#pragma unroll
            for (int mi = 0; mi < 4; mi++)
                ldsm4(af[mi][0], af[mi][1], af[mi][2], af[mi][3],
                      sA + (wm * 64 + mi * 16) * ROWB + aLane + s * 32);
#pragma unroll
            for (int p = 0; p < 2; p++) {
                unsigned r0, r1, r2, r3;
                ldsm4(r0, r1, r2, r3,
                      sB + (wn * 32 + p * 16) * ROWB + bLane + s * 32);
                bf[2 * p][0] = r0; bf[2 * p][1] = r1;
                bf[2 * p + 1][0] = r2; bf[2 * p + 1][1] = r3;
            }
#pragma unroll
            for (int mi = 0; mi < 4; mi++)
#pragma unroll
                for (int ni = 0; ni < 4; ni++) mma16(acc[mi][ni], af[mi], bf[ni]);
        }
    }
    CP_WAIT0();

    // ---------------- fused epilogue ----------------
#pragma unroll
    for (int mi = 0; mi < 4; mi++) {
        const int r0 = wm * 64 + mi * 16 + g;
        const int r1 = r0 + 8;
        const float cv0 = uc ? cov[rowBase + r0] : 0.f;
        const float cv1 = uc ? cov[rowBase + r1] : 0.f;
        float s0 = 0.f, s1 = 0.f;
#pragma unroll
        for (int ni = 0; ni < 4; ni++) {
            const int c0 = wn * 32 + ni * 8 + 2 * tig;
            const int c1 = c0 + 1;
            const float b0 = sBias[c0], b1 = sBias[c1];
            const float w0 = sWc[c0],  w1 = sWc[c1];
            const float v0 = sV[c0],   v1 = sV[c1];
            s0 += fast_tanh(acc[mi][ni][0] + b0 + cv0 * w0) * v0
                + fast_tanh(acc[mi][ni][1] + b1 + cv0 * w1) * v1;
            s1 += fast_tanh(acc[mi][ni][2] + b0 + cv1 * w0) * v0
                + fast_tanh(acc[mi][ni][3] + b1 + cv1 * w1) * v1;
        }
        s0 += __shfl_xor_sync(0xFFFFFFFFu, s0, 1);
        s0 += __shfl_xor_sync(0xFFFFFFFFu, s0, 2);
        s1 += __shfl_xor_sync(0xFFFFFFFFu, s1, 1);
        s1 += __shfl_xor_sync(0xFFFFFFFFu, s1, 2);
        if (tig == 0) {
            atomicAdd(&sRow[r0], s0);
            atomicAdd(&sRow[r1], s1);
        }
    }
    __syncthreads();
    if (tid < 128) atomicAdd(&g_score[rowBase + tid], sRow[tid]);
}

// ---------------------------------------------------------------------------
// Kernel 3: masked softmax over L per batch; writes attn and coverage outputs
// ---------------------------------------------------------------------------
__global__ void softmax_kernel(const float* __restrict__ cov,
                               const float* __restrict__ Vb,
                               const int* __restrict__ mask,
                               const int* __restrict__ ucp,
                               float* __restrict__ attn,
                               float* __restrict__ covOut) {
    __shared__ float red[256];
    const int b = blockIdx.x;
    const int tid = threadIdx.x;
    const float vb = Vb[0];
    const int uc = *ucp;

    float vals[8];
    float mx = -INFINITY;
#pragma unroll
    for (int i = 0; i < 8; i++) {
        const int l = tid + i * 256;
        const float s = (g_score[b * Ll + l] + vb) * (float)mask[b * Ll + l];
        vals[i] = s;
        mx = fmaxf(mx, s);
    }
    red[tid] = mx;
    __syncthreads();
    for (int s = 128; s > 0; s >>= 1) {
        if (tid < s) red[tid] = fmaxf(red[tid], red[tid + s]);
        __syncthreads();
    }
    mx = red[0];
    __syncthreads();

    float sum = 0.f;
#pragma unroll
    for (int i = 0; i < 8; i++) {
        vals[i] = expf(vals[i] - mx);
        sum += vals[i];
    }
    red[tid] = sum;
    __syncthreads();
    for (int s = 128; s > 0; s >>= 1) {
        if (tid < s) red[tid] += red[tid + s];
        __syncthreads();
    }
    const float inv = 1.f / red[0];

#pragma unroll
    for (int i = 0; i < 8; i++) {
        const int l = tid + i * 256;
        const float w = vals[i] * inv;
        attn[b * Ll + l] = w;
        covOut[b * Ll + l] = w + (uc ? cov[b * Ll + l] : 0.f);
    }
}

// ---------------------------------------------------------------------------
// Kernel 4: context[b,e] += sum_{l in chunk} attn[b,l] * enc[b,l,e]
// grid (32, 32), 256 threads, float4, atomics into pre-zeroed ctx
// ---------------------------------------------------------------------------
__global__ void __launch_bounds__(256)
context_kernel(const float* __restrict__ enc,
               const float* __restrict__ attn,
               float* __restrict__ ctx) {
    __shared__ float w[64];
    const int b = blockIdx.y;
    const int l0 = blockIdx.x * 64;
    if (threadIdx.x < 64) w[threadIdx.x] = attn[b * Ll + l0 + threadIdx.x];
    __syncthreads();

    const float4* ep = (const float4*)(enc + ((size_t)b * Ll + l0) * Ee) + threadIdx.x;
    float4 acc = make_float4(0.f, 0.f, 0.f, 0.f);
#pragma unroll 4
    for (int l = 0; l < 64; l++) {
        const float wv = w[l];
        const float4 v = ep[(size_t)l * 256];
        acc.x += wv * v.x; acc.y += wv * v.y; acc.z += wv * v.z; acc.w += wv * v.w;
    }
    float* c = ctx + b * Ee + threadIdx.x * 4;
    atomicAdd(c + 0, acc.x);
    atomicAdd(c + 1, acc.y);
    atomicAdd(c + 2, acc.z);
    atomicAdd(c + 3, acc.w);
}

// ---------------------------------------------------------------------------
extern "C" void kernel_launch(void* const* d_in, const int* in_sizes, int n_in,
                              void* d_out, int out_size) {
    const float* dec  = (const float*)d_in[0];
    const float* enc  = (const float*)d_in[1];
    const float* cov  = (const float*)d_in[2];
    const float* Wsk  = (const float*)d_in[3];
    const float* Wsb  = (const float*)d_in[4];
    const float* Whk  = (const float*)d_in[5];
    const float* Whb  = (const float*)d_in[6];
    const float* Wck  = (const float*)d_in[7];
    const float* Wcb  = (const float*)d_in[8];
    const float* Vk   = (const float*)d_in[9];
    const float* Vb   = (const float*)d_in[10];
    const int*   mask = (const int*)d_in[11];
    const int*   ucp  = (const int*)d_in[12];

    float* out    = (float*)d_out;
    float* ctx    = out;                       // [32, 1024]
    float* attn   = out + Bb * Ee;             // [32, 2048]
    float* covOut = attn + Bb * Ll;            // [32, 2048]

    cudaFuncSetAttribute(gemm_score_h, cudaFuncAttributeMaxDynamicSharedMemorySize,
                         SMEM_TOTAL);

    conv_enc<<<32768, 256>>>(enc);
    transpose_ws<<<dim3(32, 32), dim3(32, 8)>>>(Wsk);
    hw_kernel<<<dim3(4, 32), 256>>>(dec, Whk, Wsb, Whb, Wcb, ucp, ctx);
    gemm_score_h<<<dim3(Uu / BN, (Bb * Ll) / BM), 512, SMEM_TOTAL>>>(Wck, Vk, cov, ucp);
    softmax_kernel<<<Bb, 256>>>(cov, Vb, mask, ucp, attn, covOut);
    context_kernel<<<dim3(32, Bb), 256>>>(enc, attn, ctx);
}

// round 5
// speedup vs baseline: 3.1479x; 1.0721x over previous
#include <cuda_runtime.h>
#include <cuda_fp16.h>
#include <math.h>
#include <stdint.h>

// Problem dims (fixed by the dataset)
#define Bb 32
#define Ll 2048
#define Ee 1024
#define Uu 1024

// GEMM tiling (fp16 mma.sync m16n8k16)
#define BM 128
#define BN 256
#define BKH 64                       // 64 halves per k-tile (128B data per row)
#define NKT (Ee / BKH)               // 16 k-tiles
#define ROWB 144                     // 128B data + 16B pad -> conflict-free ldmatrix
#define A_STAGE_BYTES (BM * ROWB)    // 18432
#define B_STAGE_BYTES (BN * ROWB)    // 36864
#define STAGE_BYTES (A_STAGE_BYTES + B_STAGE_BYTES)   // 55296
#define NSTAGE 3
#define SM_TILES_BYTES (NSTAGE * STAGE_BYTES)          // 165888
#define SM_BIAS_OFF (SM_TILES_BYTES)
#define SM_WC_OFF   (SM_BIAS_OFF + 1024)
#define SM_V_OFF    (SM_WC_OFF + 1024)
#define SM_ROW_OFF  (SM_V_OFF + 1024)
#define SMEM_TOTAL  (SM_ROW_OFF + 512)                 // 169472 bytes

// Scratch (no cudaMalloc allowed)
__device__ float  g_score[Bb * Ll];
__device__ float  g_hW[Bb * Uu];
__device__ __half g_encH[(size_t)Bb * Ll * Ee];   // fp16 copy of enc (128MB)
__device__ __half g_WsTH[Uu * Ee];                // transposed Ws in fp16

// ---------------------------------------------------------------------------
__device__ __forceinline__ uint32_t smem_to_u32(const void* p) {
    uint32_t a;
    asm("{ .reg .u64 t; cvta.to.shared.u64 t, %1; cvt.u32.u64 %0, t; }" : "=r"(a) : "l"(p));
    return a;
}
__device__ __forceinline__ void cp16(uint32_t dst, const void* src) {
    asm volatile("cp.async.cg.shared.global [%0], [%1], 16;" :: "r"(dst), "l"(src) : "memory");
}
#define CP_COMMIT() asm volatile("cp.async.commit_group;" ::: "memory")
#define CP_WAIT1()  asm volatile("cp.async.wait_group 1;" ::: "memory")
#define CP_WAIT0()  asm volatile("cp.async.wait_group 0;" ::: "memory")

__device__ __forceinline__ void ldsm4(unsigned& r0, unsigned& r1, unsigned& r2,
                                      unsigned& r3, uint32_t addr) {
    asm volatile("ldmatrix.sync.aligned.m8n8.x4.shared.b16 {%0,%1,%2,%3}, [%4];"
                 : "=r"(r0), "=r"(r1), "=r"(r2), "=r"(r3) : "r"(addr));
}

__device__ __forceinline__ void mma16(float d[4], const unsigned a[4], const unsigned b[2]) {
    asm volatile(
        "mma.sync.aligned.m16n8k16.row.col.f32.f16.f16.f32 "
        "{%0,%1,%2,%3},{%4,%5,%6,%7},{%8,%9},{%0,%1,%2,%3};"
        : "+f"(d[0]), "+f"(d[1]), "+f"(d[2]), "+f"(d[3])
        : "r"(a[0]), "r"(a[1]), "r"(a[2]), "r"(a[3]), "r"(b[0]), "r"(b[1]));
}

__device__ __forceinline__ float fast_tanh(float x) {
    const float t = __expf(2.f * x);
    return 1.f - __fdividef(2.f, t + 1.f);
}

// ---------------------------------------------------------------------------
// Kernel 0a: enc -> fp16 copy. 8 floats/thread, grid 32768 x 256
// ---------------------------------------------------------------------------
__global__ void __launch_bounds__(256)
conv_enc(const float* __restrict__ enc) {
    const size_t i = ((size_t)blockIdx.x * 256 + threadIdx.x) * 8;
    const float4 v0 = *(const float4*)(enc + i);
    const float4 v1 = *(const float4*)(enc + i + 4);
    __half2 h0 = __floats2half2_rn(v0.x, v0.y);
    __half2 h1 = __floats2half2_rn(v0.z, v0.w);
    __half2 h2 = __floats2half2_rn(v1.x, v1.y);
    __half2 h3 = __floats2half2_rn(v1.z, v1.w);
    uint4 o;
    o.x = *(uint32_t*)&h0; o.y = *(uint32_t*)&h1;
    o.z = *(uint32_t*)&h2; o.w = *(uint32_t*)&h3;
    *(uint4*)(g_encH + i) = o;
}

// ---------------------------------------------------------------------------
// Kernel 0b: WsTH[u][e] = half(Ws[e][u]).  grid (32,32), block (32,8)
// ---------------------------------------------------------------------------
__global__ void transpose_ws(const float* __restrict__ Ws) {
    __shared__ float t[32][33];
    const int bx = blockIdx.x, by = blockIdx.y;
    const int tx = threadIdx.x, ty = threadIdx.y;
#pragma unroll
    for (int j = 0; j < 4; j++)
        t[ty + j * 8][tx] = Ws[(size_t)(by * 32 + ty + j * 8) * Uu + bx * 32 + tx];
    __syncthreads();
#pragma unroll
    for (int j = 0; j < 4; j++)
        g_WsTH[(size_t)(bx * 32 + ty + j * 8) * Ee + by * 32 + tx] =
            __float2half_rn(t[tx][ty + j * 8]);
}

// ---------------------------------------------------------------------------
// Kernel 1: g_hW[b,u] = dec[b,:]@Wh[:,u] + Ws_b + Wh_b (+Wc_b); zero score & ctx
// ---------------------------------------------------------------------------
__global__ void hw_kernel(const float* __restrict__ dec,
                          const float* __restrict__ Wh,
                          const float* __restrict__ Wsb,
                          const float* __restrict__ Whb,
                          const float* __restrict__ Wcb,
                          const int* __restrict__ ucp,
                          float* __restrict__ ctx) {
    __shared__ float sdec[Ee];
    const int b = blockIdx.y;
    const int u = blockIdx.x * 256 + threadIdx.x;

    for (int e = threadIdx.x; e < Ee; e += 256) sdec[e] = dec[b * Ee + e];
    __syncthreads();

    float acc = 0.f;
#pragma unroll 8
    for (int e = 0; e < Ee; e++) acc += sdec[e] * Wh[(size_t)e * Uu + u];

    const int uc = *ucp;
    g_hW[b * Uu + u] = acc + Wsb[u] + Whb[u] + (uc ? Wcb[u] : 0.f);

    const int idx = (blockIdx.y * gridDim.x + blockIdx.x) * 256 + threadIdx.x;
    g_score[idx * 2 + 0] = 0.f;
    g_score[idx * 2 + 1] = 0.f;
    ctx[idx] = 0.f;
}

// ---------------------------------------------------------------------------
// Kernel 2: fp16 mma.sync GEMM (128x256 block, 16 warps of 64x32) + fused
// tanh/V epilogue -> score.  512 threads, 3-stage cp.async, BK=64.
// ---------------------------------------------------------------------------
__device__ __forceinline__ void stage_tile(uint32_t smBase, int buf,
                                           const __half* __restrict__ aG,
                                           const __half* __restrict__ bG,
                                           int kt, int tid) {
    const uint32_t st = smBase + buf * STAGE_BYTES;
    // A: 128 rows x 8 chunks = 1024 chunks, 2 per thread
#pragma unroll
    for (int i = 0; i < 2; i++) {
        const int c = tid + i * 512;
        const int r = c >> 3, ch = c & 7;
        cp16(st + r * ROWB + ch * 16, aG + (size_t)r * Ee + kt * BKH + ch * 8);
    }
    // B: 256 rows x 8 chunks = 2048 chunks, 4 per thread
    const uint32_t bO = st + A_STAGE_BYTES;
#pragma unroll
    for (int i = 0; i < 4; i++) {
        const int c = tid + i * 512;
        const int r = c >> 3, ch = c & 7;
        cp16(bO + r * ROWB + ch * 16, bG + (size_t)r * Ee + kt * BKH + ch * 8);
    }
}

__global__ void __launch_bounds__(512, 1)
gemm_score_h(const float* __restrict__ Wc,
             const float* __restrict__ Vk,
             const float* __restrict__ cov,
             const int* __restrict__ ucp) {
    extern __shared__ char smem[];
    const uint32_t smBase = smem_to_u32(smem);
    const int tid  = threadIdx.x;
    const int wid  = tid >> 5;
    const int lane = tid & 31;
    const int g    = lane >> 2;
    const int tig  = lane & 3;
    const int wm   = wid >> 3;     // 0..1 (M)
    const int wn   = wid & 7;      // 0..7 (N)

    const int rowBase = blockIdx.y * BM;
    const int colBase = blockIdx.x * BN;
    const int b = rowBase >> 11;
    const int uc = *ucp;

    float* sBias = (float*)(smem + SM_BIAS_OFF);
    float* sWc   = (float*)(smem + SM_WC_OFF);
    float* sV    = (float*)(smem + SM_V_OFF);
    float* sRow  = (float*)(smem + SM_ROW_OFF);

    if (tid < 256) {
        const int u = colBase + tid;
        sBias[tid] = g_hW[b * Uu + u];
        sWc[tid]   = uc ? Wc[u] : 0.f;
        sV[tid]    = Vk[u];
    }
    if (tid < 128) sRow[tid] = 0.f;

    const __half* aG = g_encH + (size_t)rowBase * Ee;
    const __half* bG = g_WsTH + (size_t)colBase * Ee;

    // ldmatrix lane-address components (relative to tile bases)
    const uint32_t aLane = (uint32_t)((lane & 15) * ROWB + (lane >> 4) * 16);
    const uint32_t bLane = (uint32_t)((((lane >> 4) << 3) + (lane & 7)) * ROWB
                                      + ((lane >> 3) & 1) * 16);

    stage_tile(smBase, 0, aG, bG, 0, tid); CP_COMMIT();
    stage_tile(smBase, 1, aG, bG, 1, tid); CP_COMMIT();

    float acc[4][4][4];
#pragma unroll
    for (int i = 0; i < 4; i++)
#pragma unroll
        for (int j = 0; j < 4; j++)
#pragma unroll
            for (int k = 0; k < 4; k++) acc[i][j][k] = 0.f;

    int buf = 0;
    for (int kt = 0; kt < NKT; kt++) {
        CP_WAIT1();
        __syncthreads();

        if (kt + 2 < NKT) {
            int nb = buf + 2; if (nb >= NSTAGE) nb -= NSTAGE;
            stage_tile(smBase, nb, aG, bG, kt + 2, tid);
        }
        CP_COMMIT();   // possibly-empty commit keeps wait_group arithmetic valid

        const uint32_t sA = smBase + buf * STAGE_BYTES;
        const uint32_t sB = sA + A_STAGE_BYTES;

#pragma unroll
        for (int s = 0; s < 4; s++) {
            unsigned af[4][4], bf[4][2];
#pragma unroll
            for (int mi = 0; mi < 4; mi++)
                ldsm4(af[mi][0], af[mi][1], af[mi][2], af[mi][3],
                      sA + (wm * 64 + mi * 16) * ROWB + aLane + s * 32);
#pragma unroll
            for (int p = 0; p < 2; p++) {
                unsigned r0, r1, r2, r3;
                ldsm4(r0, r1, r2, r3,
                      sB + (wn * 32 + p * 16) * ROWB + bLane + s * 32);
                bf[2 * p][0] = r0; bf[2 * p][1] = r1;
                bf[2 * p + 1][0] = r2; bf[2 * p + 1][1] = r3;
            }
#pragma unroll
            for (int mi = 0; mi < 4; mi++)
#pragma unroll
                for (int ni = 0; ni < 4; ni++) mma16(acc[mi][ni], af[mi], bf[ni]);
        }

        if (++buf == NSTAGE) buf = 0;
    }
    CP_WAIT0();

    // ---------------- fused epilogue ----------------
#pragma unroll
    for (int mi = 0; mi < 4; mi++) {
        const int r0 = wm * 64 + mi * 16 + g;
        const int r1 = r0 + 8;
        const float cv0 = uc ? cov[rowBase + r0] : 0.f;
        const float cv1 = uc ? cov[rowBase + r1] : 0.f;
        float s0 = 0.f, s1 = 0.f;
#pragma unroll
        for (int ni = 0; ni < 4; ni++) {
            const int c0 = wn * 32 + ni * 8 + 2 * tig;
            const int c1 = c0 + 1;
            const float b0 = sBias[c0], b1 = sBias[c1];
            const float w0 = sWc[c0],  w1 = sWc[c1];
            const float v0 = sV[c0],   v1 = sV[c1];
            s0 += fast_tanh(acc[mi][ni][0] + b0 + cv0 * w0) * v0
                + fast_tanh(acc[mi][ni][1] + b1 + cv0 * w1) * v1;
            s1 += fast_tanh(acc[mi][ni][2] + b0 + cv1 * w0) * v0
                + fast_tanh(acc[mi][ni][3] + b1 + cv1 * w1) * v1;
        }
        s0 += __shfl_xor_sync(0xFFFFFFFFu, s0, 1);
        s0 += __shfl_xor_sync(0xFFFFFFFFu, s0, 2);
        s1 += __shfl_xor_sync(0xFFFFFFFFu, s1, 1);
        s1 += __shfl_xor_sync(0xFFFFFFFFu, s1, 2);
        if (tig == 0) {
            atomicAdd(&sRow[r0], s0);
            atomicAdd(&sRow[r1], s1);
        }
    }
    __syncthreads();
    if (tid < 128) atomicAdd(&g_score[rowBase + tid], sRow[tid]);
}

// ---------------------------------------------------------------------------
// Kernel 3: masked softmax over L per batch; writes attn and coverage outputs
// ---------------------------------------------------------------------------
__global__ void softmax_kernel(const float* __restrict__ cov,
                               const float* __restrict__ Vb,
                               const int* __restrict__ mask,
                               const int* __restrict__ ucp,
                               float* __restrict__ attn,
                               float* __restrict__ covOut) {
    __shared__ float red[256];
    const int b = blockIdx.x;
    const int tid = threadIdx.x;
    const float vb = Vb[0];
    const int uc = *ucp;

    float vals[8];
    float mx = -INFINITY;
#pragma unroll
    for (int i = 0; i < 8; i++) {
        const int l = tid + i * 256;
        const float s = (g_score[b * Ll + l] + vb) * (float)mask[b * Ll + l];
        vals[i] = s;
        mx = fmaxf(mx, s);
    }
    red[tid] = mx;
    __syncthreads();
    for (int s = 128; s > 0; s >>= 1) {
        if (tid < s) red[tid] = fmaxf(red[tid], red[tid + s]);
        __syncthreads();
    }
    mx = red[0];
    __syncthreads();

    float sum = 0.f;
#pragma unroll
    for (int i = 0; i < 8; i++) {
        vals[i] = expf(vals[i] - mx);
        sum += vals[i];
    }
    red[tid] = sum;
    __syncthreads();
    for (int s = 128; s > 0; s >>= 1) {
        if (tid < s) red[tid] += red[tid + s];
        __syncthreads();
    }
    const float inv = 1.f / red[0];

#pragma unroll
    for (int i = 0; i < 8; i++) {
        const int l = tid + i * 256;
        const float w = vals[i] * inv;
        attn[b * Ll + l] = w;
        covOut[b * Ll + l] = w + (uc ? cov[b * Ll + l] : 0.f);
    }
}

// ---------------------------------------------------------------------------
// Kernel 4: context[b,e] += sum_{l in chunk} attn[b,l] * enc[b,l,e]
// grid (32, 32), 256 threads, float4, atomics into pre-zeroed ctx
// ---------------------------------------------------------------------------
__global__ void __launch_bounds__(256)
context_kernel(const float* __restrict__ enc,
               const float* __restrict__ attn,
               float* __restrict__ ctx) {
    __shared__ float w[64];
    const int b = blockIdx.y;
    const int l0 = blockIdx.x * 64;
    if (threadIdx.x < 64) w[threadIdx.x] = attn[b * Ll + l0 + threadIdx.x];
    __syncthreads();

    const float4* ep = (const float4*)(enc + ((size_t)b * Ll + l0) * Ee) + threadIdx.x;
    float4 acc = make_float4(0.f, 0.f, 0.f, 0.f);
#pragma unroll 4
    for (int l = 0; l < 64; l++) {
        const float wv = w[l];
        const float4 v = ep[(size_t)l * 256];
        acc.x += wv * v.x; acc.y += wv * v.y; acc.z += wv * v.z; acc.w += wv * v.w;
    }
    float* c = ctx + b * Ee + threadIdx.x * 4;
    atomicAdd(c + 0, acc.x);
    atomicAdd(c + 1, acc.y);
    atomicAdd(c + 2, acc.z);
    atomicAdd(c + 3, acc.w);
}

// ---------------------------------------------------------------------------
extern "C" void kernel_launch(void* const* d_in, const int* in_sizes, int n_in,
                              void* d_out, int out_size) {
    const float* dec  = (const float*)d_in[0];
    const float* enc  = (const float*)d_in[1];
    const float* cov  = (const float*)d_in[2];
    const float* Wsk  = (const float*)d_in[3];
    const float* Wsb  = (const float*)d_in[4];
    const float* Whk  = (const float*)d_in[5];
    const float* Whb  = (const float*)d_in[6];
    const float* Wck  = (const float*)d_in[7];
    const float* Wcb  = (const float*)d_in[8];
    const float* Vk   = (const float*)d_in[9];
    const float* Vb   = (const float*)d_in[10];
    const int*   mask = (const int*)d_in[11];
    const int*   ucp  = (const int*)d_in[12];

    float* out    = (float*)d_out;
    float* ctx    = out;                       // [32, 1024]
    float* attn   = out + Bb * Ee;             // [32, 2048]
    float* covOut = attn + Bb * Ll;            // [32, 2048]

    cudaFuncSetAttribute(gemm_score_h, cudaFuncAttributeMaxDynamicSharedMemorySize,
                         SMEM_TOTAL);

    conv_enc<<<32768, 256>>>(enc);
    transpose_ws<<<dim3(32, 32), dim3(32, 8)>>>(Wsk);
    hw_kernel<<<dim3(4, 32), 256>>>(dec, Whk, Wsb, Whb, Wcb, ucp, ctx);
    gemm_score_h<<<dim3(Uu / BN, (Bb * Ll) / BM), 512, SMEM_TOTAL>>>(Wck, Vk, cov, ucp);
    softmax_kernel<<<Bb, 256>>>(cov, Vb, mask, ucp, attn, covOut);
    context_kernel<<<dim3(32, Bb), 256>>>(enc, attn, ctx);
}

// round 6
// speedup vs baseline: 3.4201x; 1.0865x over previous
#include <cuda_runtime.h>
#include <cuda_fp16.h>
#include <math.h>
#include <stdint.h>

// Problem dims (fixed by the dataset)
#define Bb 32
#define Ll 2048
#define Ee 1024
#define Uu 1024

// GEMM tiling (fp16 mma.sync m16n8k16), 2 CTAs/SM
#define BM 128
#define BN 128
#define BKH 64                       // 64 halves per k-tile (128B data per row)
#define NKT (Ee / BKH)               // 16 k-tiles
#define ROWB 144                     // 128B data + 16B pad -> conflict-free ldmatrix
#define A_STAGE_BYTES (BM * ROWB)    // 18432
#define B_STAGE_BYTES (BN * ROWB)    // 18432
#define STAGE_BYTES (A_STAGE_BYTES + B_STAGE_BYTES)   // 36864
#define NSTAGE 3
#define SM_TILES_BYTES (NSTAGE * STAGE_BYTES)          // 110592
#define SM_BIAS_OFF (SM_TILES_BYTES)                   // 128 floats
#define SM_WC_OFF   (SM_BIAS_OFF + 512)
#define SM_V_OFF    (SM_WC_OFF + 512)
#define SM_ROW_OFF  (SM_V_OFF + 512)
#define SMEM_TOTAL  (SM_ROW_OFF + 512)                 // 112640 bytes (2/SM)

// Scratch (no cudaMalloc allowed)
__device__ float  g_score[Bb * Ll];
__device__ float  g_hW[Bb * Uu];
__device__ __half g_encH[(size_t)Bb * Ll * Ee];   // fp16 copy of enc (128MB)
__device__ __half g_WsTH[Uu * Ee];                // transposed Ws in fp16

// ---------------------------------------------------------------------------
__device__ __forceinline__ uint32_t smem_to_u32(const void* p) {
    uint32_t a;
    asm("{ .reg .u64 t; cvta.to.shared.u64 t, %1; cvt.u32.u64 %0, t; }" : "=r"(a) : "l"(p));
    return a;
}
__device__ __forceinline__ void cp16(uint32_t dst, const void* src) {
    asm volatile("cp.async.cg.shared.global [%0], [%1], 16;" :: "r"(dst), "l"(src) : "memory");
}
#define CP_COMMIT() asm volatile("cp.async.commit_group;" ::: "memory")
#define CP_WAIT1()  asm volatile("cp.async.wait_group 1;" ::: "memory")
#define CP_WAIT0()  asm volatile("cp.async.wait_group 0;" ::: "memory")

__device__ __forceinline__ void ldsm4(unsigned& r0, unsigned& r1, unsigned& r2,
                                      unsigned& r3, uint32_t addr) {
    asm volatile("ldmatrix.sync.aligned.m8n8.x4.shared.b16 {%0,%1,%2,%3}, [%4];"
                 : "=r"(r0), "=r"(r1), "=r"(r2), "=r"(r3) : "r"(addr));
}

__device__ __forceinline__ void mma16(float d[4], const unsigned a[4], const unsigned b[2]) {
    asm volatile(
        "mma.sync.aligned.m16n8k16.row.col.f32.f16.f16.f32 "
        "{%0,%1,%2,%3},{%4,%5,%6,%7},{%8,%9},{%0,%1,%2,%3};"
        : "+f"(d[0]), "+f"(d[1]), "+f"(d[2]), "+f"(d[3])
        : "r"(a[0]), "r"(a[1]), "r"(a[2]), "r"(a[3]), "r"(b[0]), "r"(b[1]));
}

__device__ __forceinline__ float fast_tanh(float x) {
    const float t = __expf(2.f * x);
    return 1.f - __fdividef(2.f, t + 1.f);
}

// ---------------------------------------------------------------------------
// Kernel 0a: enc -> fp16 copy. 8 floats/thread, grid 32768 x 256
// ---------------------------------------------------------------------------
__global__ void __launch_bounds__(256)
conv_enc(const float* __restrict__ enc) {
    const size_t i = ((size_t)blockIdx.x * 256 + threadIdx.x) * 8;
    const float4 v0 = *(const float4*)(enc + i);
    const float4 v1 = *(const float4*)(enc + i + 4);
    __half2 h0 = __floats2half2_rn(v0.x, v0.y);
    __half2 h1 = __floats2half2_rn(v0.z, v0.w);
    __half2 h2 = __floats2half2_rn(v1.x, v1.y);
    __half2 h3 = __floats2half2_rn(v1.z, v1.w);
    uint4 o;
    o.x = *(uint32_t*)&h0; o.y = *(uint32_t*)&h1;
    o.z = *(uint32_t*)&h2; o.w = *(uint32_t*)&h3;
    *(uint4*)(g_encH + i) = o;
}

// ---------------------------------------------------------------------------
// Kernel 0b: WsTH[u][e] = half(Ws[e][u]).  grid (32,32), block (32,8)
// ---------------------------------------------------------------------------
__global__ void transpose_ws(const float* __restrict__ Ws) {
    __shared__ float t[32][33];
    const int bx = blockIdx.x, by = blockIdx.y;
    const int tx = threadIdx.x, ty = threadIdx.y;
#pragma unroll
    for (int j = 0; j < 4; j++)
        t[ty + j * 8][tx] = Ws[(size_t)(by * 32 + ty + j * 8) * Uu + bx * 32 + tx];
    __syncthreads();
#pragma unroll
    for (int j = 0; j < 4; j++)
        g_WsTH[(size_t)(bx * 32 + ty + j * 8) * Ee + by * 32 + tx] =
            __float2half_rn(t[tx][ty + j * 8]);
}

// ---------------------------------------------------------------------------
// Kernel 1: g_hW[b,u] = dec[b,:]@Wh[:,u] + Ws_b + Wh_b (+Wc_b); zero score & ctx
// ---------------------------------------------------------------------------
__global__ void hw_kernel(const float* __restrict__ dec,
                          const float* __restrict__ Wh,
                          const float* __restrict__ Wsb,
                          const float* __restrict__ Whb,
                          const float* __restrict__ Wcb,
                          const int* __restrict__ ucp,
                          float* __restrict__ ctx) {
    __shared__ float sdec[Ee];
    const int b = blockIdx.y;
    const int u = blockIdx.x * 256 + threadIdx.x;

    for (int e = threadIdx.x; e < Ee; e += 256) sdec[e] = dec[b * Ee + e];
    __syncthreads();

    float acc = 0.f;
#pragma unroll 8
    for (int e = 0; e < Ee; e++) acc += sdec[e] * Wh[(size_t)e * Uu + u];

    const int uc = *ucp;
    g_hW[b * Uu + u] = acc + Wsb[u] + Whb[u] + (uc ? Wcb[u] : 0.f);

    const int idx = (blockIdx.y * gridDim.x + blockIdx.x) * 256 + threadIdx.x;
    g_score[idx * 2 + 0] = 0.f;
    g_score[idx * 2 + 1] = 0.f;
    ctx[idx] = 0.f;
}

// ---------------------------------------------------------------------------
// Kernel 2: fp16 mma.sync GEMM (128x128 block, 8 warps of 64x32, 2 CTAs/SM)
// + fused tanh/V epilogue -> score. 256 threads, 3-stage cp.async, BK=64,
// A-fragment register double-buffering across k-slices.
// ---------------------------------------------------------------------------
__device__ __forceinline__ void stage_tile(uint32_t smBase, int buf,
                                           const __half* __restrict__ aG,
                                           const __half* __restrict__ bG,
                                           int kt, int tid) {
    const uint32_t st = smBase + buf * STAGE_BYTES;
    // A: 128 rows x 8 chunks = 1024 chunks, 4 per thread
#pragma unroll
    for (int i = 0; i < 4; i++) {
        const int c = tid + i * 256;
        const int r = c >> 3, ch = c & 7;
        cp16(st + r * ROWB + ch * 16, aG + (size_t)r * Ee + kt * BKH + ch * 8);
    }
    // B: 128 rows x 8 chunks = 1024 chunks, 4 per thread
    const uint32_t bO = st + A_STAGE_BYTES;
#pragma unroll
    for (int i = 0; i < 4; i++) {
        const int c = tid + i * 256;
        const int r = c >> 3, ch = c & 7;
        cp16(bO + r * ROWB + ch * 16, bG + (size_t)r * Ee + kt * BKH + ch * 8);
    }
}

__global__ void __launch_bounds__(256, 2)
gemm_score_h(const float* __restrict__ Wc,
             const float* __restrict__ Vk,
             const float* __restrict__ cov,
             const int* __restrict__ ucp) {
    extern __shared__ char smem[];
    const uint32_t smBase = smem_to_u32(smem);
    const int tid  = threadIdx.x;
    const int wid  = tid >> 5;
    const int lane = tid & 31;
    const int g    = lane >> 2;
    const int tig  = lane & 3;
    const int wm   = wid >> 2;     // 0..1 (M)
    const int wn   = wid & 3;      // 0..3 (N)

    const int rowBase = blockIdx.y * BM;
    const int colBase = blockIdx.x * BN;
    const int b = rowBase >> 11;
    const int uc = *ucp;

    float* sBias = (float*)(smem + SM_BIAS_OFF);
    float* sWc   = (float*)(smem + SM_WC_OFF);
    float* sV    = (float*)(smem + SM_V_OFF);
    float* sRow  = (float*)(smem + SM_ROW_OFF);

    if (tid < 128) {
        const int u = colBase + tid;
        sBias[tid] = g_hW[b * Uu + u];
        sWc[tid]   = uc ? Wc[u] : 0.f;
        sV[tid]    = Vk[u];
        sRow[tid]  = 0.f;
    }

    const __half* aG = g_encH + (size_t)rowBase * Ee;
    const __half* bG = g_WsTH + (size_t)colBase * Ee;

    // ldmatrix lane-address components (relative to tile bases)
    const uint32_t aLane = (uint32_t)((lane & 15) * ROWB + (lane >> 4) * 16);
    const uint32_t bLane = (uint32_t)((((lane >> 4) << 3) + (lane & 7)) * ROWB
                                      + ((lane >> 3) & 1) * 16);

    stage_tile(smBase, 0, aG, bG, 0, tid); CP_COMMIT();
    stage_tile(smBase, 1, aG, bG, 1, tid); CP_COMMIT();

    float acc[4][4][4];
#pragma unroll
    for (int i = 0; i < 4; i++)
#pragma unroll
        for (int j = 0; j < 4; j++)
#pragma unroll
            for (int k = 0; k < 4; k++) acc[i][j][k] = 0.f;

    int buf = 0;
    for (int kt = 0; kt < NKT; kt++) {
        CP_WAIT1();
        __syncthreads();

        if (kt + 2 < NKT) {
            int nb = buf + 2; if (nb >= NSTAGE) nb -= NSTAGE;
            stage_tile(smBase, nb, aG, bG, kt + 2, tid);
        }
        CP_COMMIT();   // possibly-empty commit keeps wait_group arithmetic valid

        const uint32_t sA = smBase + buf * STAGE_BYTES;
        const uint32_t sB = sA + A_STAGE_BYTES;
        const uint32_t aBase = sA + (wm * 64) * ROWB + aLane;
        const uint32_t bBase = sB + (wn * 32) * ROWB + bLane;

        // double-buffered A fragments across the 4 k-slices
        unsigned af[2][4][4];
        unsigned bf[4][2];

#pragma unroll
        for (int mi = 0; mi < 4; mi++)
            ldsm4(af[0][mi][0], af[0][mi][1], af[0][mi][2], af[0][mi][3],
                  aBase + mi * 16 * ROWB);

#pragma unroll
        for (int s = 0; s < 4; s++) {
            // B fragments for this slice
#pragma unroll
            for (int p = 0; p < 2; p++) {
                unsigned r0, r1, r2, r3;
                ldsm4(r0, r1, r2, r3, bBase + p * 16 * ROWB + s * 32);
                bf[2 * p][0] = r0;     bf[2 * p][1] = r1;
                bf[2 * p + 1][0] = r2; bf[2 * p + 1][1] = r3;
            }
            // prefetch next slice's A fragments under the MMAs
            if (s < 3) {
#pragma unroll
                for (int mi = 0; mi < 4; mi++)
                    ldsm4(af[(s + 1) & 1][mi][0], af[(s + 1) & 1][mi][1],
                          af[(s + 1) & 1][mi][2], af[(s + 1) & 1][mi][3],
                          aBase + mi * 16 * ROWB + (s + 1) * 32);
            }
#pragma unroll
            for (int mi = 0; mi < 4; mi++)
#pragma unroll
                for (int ni = 0; ni < 4; ni++)
                    mma16(acc[mi][ni], af[s & 1][mi], bf[ni]);
        }

        if (++buf == NSTAGE) buf = 0;
    }
    CP_WAIT0();

    // ---------------- fused epilogue ----------------
#pragma unroll
    for (int mi = 0; mi < 4; mi++) {
        const int r0 = wm * 64 + mi * 16 + g;
        const int r1 = r0 + 8;
        const float cv0 = uc ? cov[rowBase + r0] : 0.f;
        const float cv1 = uc ? cov[rowBase + r1] : 0.f;
        float s0 = 0.f, s1 = 0.f;
#pragma unroll
        for (int ni = 0; ni < 4; ni++) {
            const int c0 = wn * 32 + ni * 8 + 2 * tig;
            const int c1 = c0 + 1;
            const float b0 = sBias[c0], b1 = sBias[c1];
            const float w0 = sWc[c0],  w1 = sWc[c1];
            const float v0 = sV[c0],   v1 = sV[c1];
            s0 += fast_tanh(acc[mi][ni][0] + b0 + cv0 * w0) * v0
                + fast_tanh(acc[mi][ni][1] + b1 + cv0 * w1) * v1;
            s1 += fast_tanh(acc[mi][ni][2] + b0 + cv1 * w0) * v0
                + fast_tanh(acc[mi][ni][3] + b1 + cv1 * w1) * v1;
        }
        s0 += __shfl_xor_sync(0xFFFFFFFFu, s0, 1);
        s0 += __shfl_xor_sync(0xFFFFFFFFu, s0, 2);
        s1 += __shfl_xor_sync(0xFFFFFFFFu, s1, 1);
        s1 += __shfl_xor_sync(0xFFFFFFFFu, s1, 2);
        if (tig == 0) {
            atomicAdd(&sRow[r0], s0);
            atomicAdd(&sRow[r1], s1);
        }
    }
    __syncthreads();
    if (tid < 128) atomicAdd(&g_score[rowBase + tid], sRow[tid]);
}

// ---------------------------------------------------------------------------
// Kernel 3: masked softmax over L per batch; writes attn and coverage outputs
// ---------------------------------------------------------------------------
__global__ void softmax_kernel(const float* __restrict__ cov,
                               const float* __restrict__ Vb,
                               const int* __restrict__ mask,
                               const int* __restrict__ ucp,
                               float* __restrict__ attn,
                               float* __restrict__ covOut) {
    __shared__ float red[256];
    const int b = blockIdx.x;
    const int tid = threadIdx.x;
    const float vb = Vb[0];
    const int uc = *ucp;

    float vals[8];
    float mx = -INFINITY;
#pragma unroll
    for (int i = 0; i < 8; i++) {
        const int l = tid + i * 256;
        const float s = (g_score[b * Ll + l] + vb) * (float)mask[b * Ll + l];
        vals[i] = s;
        mx = fmaxf(mx, s);
    }
    red[tid] = mx;
    __syncthreads();
    for (int s = 128; s > 0; s >>= 1) {
        if (tid < s) red[tid] = fmaxf(red[tid], red[tid + s]);
        __syncthreads();
    }
    mx = red[0];
    __syncthreads();

    float sum = 0.f;
#pragma unroll
    for (int i = 0; i < 8; i++) {
        vals[i] = expf(vals[i] - mx);
        sum += vals[i];
    }
    red[tid] = sum;
    __syncthreads();
    for (int s = 128; s > 0; s >>= 1) {
        if (tid < s) red[tid] += red[tid + s];
        __syncthreads();
    }
    const float inv = 1.f / red[0];

#pragma unroll
    for (int i = 0; i < 8; i++) {
        const int l = tid + i * 256;
        const float w = vals[i] * inv;
        attn[b * Ll + l] = w;
        covOut[b * Ll + l] = w + (uc ? cov[b * Ll + l] : 0.f);
    }
}

// ---------------------------------------------------------------------------
// Kernel 4: context[b,e] += sum_{l in chunk} attn[b,l] * encH[b,l,e]
// grid (32, 32), 256 threads, fp16 source, atomics into pre-zeroed ctx
// ---------------------------------------------------------------------------
__global__ void __launch_bounds__(256)
context_kernel(const float* __restrict__ attn,
               float* __restrict__ ctx) {
    __shared__ float w[64];
    const int b = blockIdx.y;
    const int l0 = blockIdx.x * 64;
    if (threadIdx.x < 64) w[threadIdx.x] = attn[b * Ll + l0 + threadIdx.x];
    __syncthreads();

    const __half2* ep = (const __half2*)(g_encH + ((size_t)b * Ll + l0) * Ee)
                        + threadIdx.x * 2;
    float4 acc = make_float4(0.f, 0.f, 0.f, 0.f);
#pragma unroll 4
    for (int l = 0; l < 64; l++) {
        const float wv = w[l];
        const uint2 raw = *(const uint2*)(ep + (size_t)l * 512);
        const float2 f0 = __half22float2(*(const __half2*)&raw.x);
        const float2 f1 = __half22float2(*(const __half2*)&raw.y);
        acc.x += wv * f0.x; acc.y += wv * f0.y;
        acc.z += wv * f1.x; acc.w += wv * f1.y;
    }
    float* c = ctx + b * Ee + threadIdx.x * 4;
    atomicAdd(c + 0, acc.x);
    atomicAdd(c + 1, acc.y);
    atomicAdd(c + 2, acc.z);
    atomicAdd(c + 3, acc.w);
}

// ---------------------------------------------------------------------------
extern "C" void kernel_launch(void* const* d_in, const int* in_sizes, int n_in,
                              void* d_out, int out_size) {
    const float* dec  = (const float*)d_in[0];
    const float* enc  = (const float*)d_in[1];
    const float* cov  = (const float*)d_in[2];
    const float* Wsk  = (const float*)d_in[3];
    const float* Wsb  = (const float*)d_in[4];
    const float* Whk  = (const float*)d_in[5];
    const float* Whb  = (const float*)d_in[6];
    const float* Wck  = (const float*)d_in[7];
    const float* Wcb  = (const float*)d_in[8];
    const float* Vk   = (const float*)d_in[9];
    const float* Vb   = (const float*)d_in[10];
    const int*   mask = (const int*)d_in[11];
    const int*   ucp  = (const int*)d_in[12];

    float* out    = (float*)d_out;
    float* ctx    = out;                       // [32, 1024]
    float* attn   = out + Bb * Ee;             // [32, 2048]
    float* covOut = attn + Bb * Ll;            // [32, 2048]

    cudaFuncSetAttribute(gemm_score_h, cudaFuncAttributeMaxDynamicSharedMemorySize,
                         SMEM_TOTAL);

    conv_enc<<<32768, 256>>>(enc);
    transpose_ws<<<dim3(32, 32), dim3(32, 8)>>>(Wsk);
    hw_kernel<<<dim3(4, 32), 256>>>(dec, Whk, Wsb, Whb, Wcb, ucp, ctx);
    gemm_score_h<<<dim3(Uu / BN, (Bb * Ll) / BM), 256, SMEM_TOTAL>>>(Wck, Vk, cov, ucp);
    softmax_kernel<<<Bb, 256>>>(cov, Vb, mask, ucp, attn, covOut);
    context_kernel<<<dim3(32, Bb), 256>>>(attn, ctx);
}